// round 15
// baseline (speedup 1.0000x reference)
#include <cuda_runtime.h>
#include <cuda_fp16.h>
#include <math.h>
#include <stdint.h>

// ============================================================================
// FullyConnectedSteerableGeometricProductLayer — Cl(3,0)
// R14 = R11 (best, 53.8us) + k_combine eliminated:
//   k_fused epilogue writes (acc + bias)*rsqrt2 directly to out.
//   GEMMs: fp16 mma.sync, 128x128 tiles, 8 warps split-ks + smem merge,
//   3-stage cp.async, left linear fused into grouped GEMM via K-extension.
// ============================================================================

#define QP (1024 * 256)
#define RSQRT2 0.70710678118654752440f

// ---------------- device scratch (static; no allocations) -------------------
__device__ float g_xr [8 * QP];            // x_right raw planes [comp][b][n]

__device__ __half g_xh [2097152];          // [comp][1024 b][256]
__device__ __half g_wrh[262144];           // [grade][256 n'][256]
// grouped B: per grade [256 mo][256*np paths | 256 w_left]
__device__ __half g_wgh[1572864];
// grouped A: per grade [(jl,b)][256*np U | 256 x]
__device__ __half g_Uh [13631488];

// ---------------- compile-time GA tables ------------------------------------
#define GA_TABLES \
  constexpr int   T_GR[8]     = {0,1,1,1,2,2,2,3};                       \
  constexpr int   T_RES[8][8] = {                                        \
    {0,1,2,3,4,5,6,7},{1,0,4,5,2,3,7,6},{2,4,0,6,1,7,3,5},               \
    {3,5,6,0,7,1,2,4},{4,2,1,7,0,6,5,3},{5,3,7,1,6,0,4,2},               \
    {6,7,3,2,5,4,0,1},{7,6,5,4,3,2,1,0}};                                \
  constexpr float T_SGN[8][8] = {                                        \
    { 1.f, 1.f, 1.f, 1.f, 1.f, 1.f, 1.f, 1.f},                           \
    { 1.f, 1.f, 1.f, 1.f, 1.f, 1.f, 1.f, 1.f},                           \
    { 1.f,-1.f, 1.f, 1.f,-1.f,-1.f, 1.f,-1.f},                           \
    { 1.f,-1.f,-1.f, 1.f, 1.f,-1.f,-1.f, 1.f},                           \
    { 1.f,-1.f, 1.f, 1.f,-1.f,-1.f, 1.f,-1.f},                           \
    { 1.f,-1.f,-1.f, 1.f, 1.f,-1.f,-1.f, 1.f},                           \
    { 1.f, 1.f,-1.f, 1.f,-1.f, 1.f,-1.f,-1.f},                           \
    { 1.f, 1.f,-1.f, 1.f,-1.f, 1.f,-1.f,-1.f}};                          \
  constexpr int   T_PLOC[4][4][4] = {                                    \
    { { 0,-1,-1,-1},{-1, 0,-1,-1},{-1,-1, 0,-1},{-1,-1,-1, 0} },         \
    { {-1, 1,-1,-1},{ 1,-1, 2,-1},{-1, 1,-1, 2},{-1,-1, 1,-1} },         \
    { {-1,-1, 2,-1},{-1, 3,-1, 4},{ 3,-1, 4,-1},{-1, 2,-1,-1} },         \
    { {-1,-1,-1, 3},{-1,-1, 5,-1},{-1, 5,-1,-1},{ 3,-1,-1,-1} } };       \
  constexpr int   T_NP[4]    = {4,6,6,4};                                \
  constexpr int   T_JLOC[8]  = {0,0,1,2,0,1,2,0};                        \
  constexpr int   T_JBASE[4] = {0,1,4,7};                                \
  constexpr int   T_LDH[4]   = {1280,1792,1792,1280};                    \
  constexpr long  T_UOFFX[4] = {0L, 1310720L, 6815744L, 12320768L};      \
  constexpr long  T_WOFFX[4] = {0L,  327680L,  786432L,  1245184L};      \
  constexpr int   T_GLOBALP[4][6] = {                                    \
    {0,4,10,16,0,0},{1,5,6,11,12,17},{2,7,8,13,14,18},{3,9,15,19,0,0} };

// ---------------- PTX helpers ------------------------------------------------
__device__ __forceinline__ uint32_t smem_u32(const void* p) {
    uint32_t a;
    asm("{ .reg .u64 t; cvta.to.shared.u64 t, %1; cvt.u32.u64 %0, t; }"
        : "=r"(a) : "l"(p));
    return a;
}
__device__ __forceinline__ void cp16(uint32_t dst, const void* src) {
    asm volatile("cp.async.cg.shared.global [%0], [%1], 16;"
                 :: "r"(dst), "l"(src));
}
__device__ __forceinline__ void cp_commit() {
    asm volatile("cp.async.commit_group;" ::: "memory");
}
template<int N>
__device__ __forceinline__ void cp_wait() {
    asm volatile("cp.async.wait_group %0;" :: "n"(N) : "memory");
}
__device__ __forceinline__ void ldsm_x4(uint32_t& r0, uint32_t& r1,
                                        uint32_t& r2, uint32_t& r3, uint32_t a) {
    asm volatile("ldmatrix.sync.aligned.m8n8.x4.shared.b16 {%0,%1,%2,%3}, [%4];"
                 : "=r"(r0), "=r"(r1), "=r"(r2), "=r"(r3) : "r"(a));
}
__device__ __forceinline__ void mma16816(float* c, uint32_t a0, uint32_t a1,
                                         uint32_t a2, uint32_t a3,
                                         uint32_t b0, uint32_t b1) {
    asm volatile("mma.sync.aligned.m16n8k16.row.col.f32.f16.f16.f32 "
                 "{%0,%1,%2,%3}, {%4,%5,%6,%7}, {%8,%9}, {%0,%1,%2,%3};"
                 : "+f"(c[0]), "+f"(c[1]), "+f"(c[2]), "+f"(c[3])
                 : "r"(a0), "r"(a1), "r"(a2), "r"(a3), "r"(b0), "r"(b1));
}
__device__ __forceinline__ uint32_t pack_h2(float a, float b) {
    __half2 h = __floats2half2_rn(a, b);
    return *reinterpret_cast<uint32_t*>(&h);
}

// ---------------- merged prep kernel -----------------------------------------
__global__ void k_prep(const float* __restrict__ x, const float* __restrict__ wr,
                       const float* __restrict__ wl, const float* __restrict__ gpw)
{
    GA_TABLES
    int blk = blockIdx.x;
    if (blk < 1024) {                                   // ---- x -> fp16
        int t = blk * 256 + threadIdx.x;                // t = b*256 + m
        int b = t >> 8, m = t & 255;
        const float4* xp = reinterpret_cast<const float4*>(x + (size_t)t * 8);
        float4 v0 = xp[0], v1 = xp[1];
        float xv[8] = {v0.x, v0.y, v0.z, v0.w, v1.x, v1.y, v1.z, v1.w};
        #pragma unroll
        for (int i = 0; i < 8; ++i)
            g_xh[(size_t)i * 262144 + (size_t)b * 256 + m] = __float2half(xv[i]);
    } else if (blk < 1280) {                            // ---- w_right / w_left(ext)
        int t = (blk - 1024) * 256 + threadIdx.x;       // t = row*256 + k
        int n = t >> 8, m = t & 255;
        float4 a = reinterpret_cast<const float4*>(wr)[t];
        float4 c = reinterpret_cast<const float4*>(wl)[t];
        float av[4] = {a.x, a.y, a.z, a.w};
        float cv[4] = {c.x, c.y, c.z, c.w};
        #pragma unroll
        for (int g = 0; g < 4; ++g) {
            g_wrh[(size_t)g * 65536 + (size_t)n * 256 + m] = __float2half(av[g]);
            g_wgh[T_WOFFX[g] + (size_t)n * T_LDH[g] + 256 * T_NP[g] + m] =
                __float2half(cv[g]);
        }
    } else {                                            // ---- gp path weights
        int t  = (blk - 1280) * 256 + threadIdx.x;      // t = mo*256 + n
        int mo = t >> 8, n = t & 255;
        float w[20];
        const float4* p4 = reinterpret_cast<const float4*>(gpw + (size_t)t * 20);
        #pragma unroll
        for (int q = 0; q < 5; ++q) {
            float4 v = p4[q];
            w[q*4+0] = v.x; w[q*4+1] = v.y; w[q*4+2] = v.z; w[q*4+3] = v.w;
        }
        #pragma unroll
        for (int g = 0; g < 4; ++g) {
            int np = T_NP[g];
            long base = T_WOFFX[g] + (long)mo * T_LDH[g] + (long)n * np;
            #pragma unroll
            for (int pl = 0; pl < 6; ++pl)
                if (pl < np) g_wgh[base + pl] = __float2half(w[T_GLOBALP[g][pl]]);
        }
    }
}

// ---------------- HMMA mainloop (3-stage cp.async, 256 thr, split-ks) --------
// C(128x128) = A(128 x K) * B^T. Chunk = 64 fp16 of K (128B rows, SW128).
// Stage = 32KB (A 16KB + B 16KB). Warps 0-3: ks{0,1}; warps 4-7: ks{2,3}.
#define STG 32768

__device__ __forceinline__ void issue_chunk(
    const char* __restrict__ A, const char* __restrict__ B,
    int ld_bytes, int koff_b, uint32_t dst, int tid)
{
    #pragma unroll
    for (int j = 0; j < 4; ++j) {
        int idx = tid + j * 256;
        int row = idx >> 3, c16 = idx & 7;
        uint32_t off = (uint32_t)(row * 128 + c16 * 16);
        off ^= (off >> 3) & 0x70;
        cp16(dst + off, A + (size_t)row * ld_bytes + koff_b + c16 * 16);
    }
    #pragma unroll
    for (int j = 0; j < 4; ++j) {
        int idx = tid + j * 256;
        int row = idx >> 3, c16 = idx & 7;
        uint32_t off = (uint32_t)(row * 128 + c16 * 16);
        off ^= (off >> 3) & 0x70;
        cp16(dst + 16384 + off, B + (size_t)row * ld_bytes + koff_b + c16 * 16);
    }
}

// warp tile 64x64: mt=4 (16-row), nt=8 (8-col); wm,wn in {0,1}; kh in {0,1}
__device__ __forceinline__ void compute_chunk(
    uint32_t smA, uint32_t smB, int lane, int wm, int wn, int kh,
    float acc[4][8][4])
{
    const uint32_t arow = (uint32_t)(wm * 64 + (lane & 15)) * 128;
    const uint32_t acol = ((lane >> 4) & 1) * 16;
    const int bm = lane >> 3, br = lane & 7;
    const uint32_t bcol = (uint32_t)(bm & 1) * 16;
    const int brow0 = wn * 64 + (bm >> 1) * 8 + br;
    #pragma unroll
    for (int ks2 = 0; ks2 < 2; ++ks2) {
        const int ks = kh * 2 + ks2;
        uint32_t af[4][4];
        #pragma unroll
        for (int mt = 0; mt < 4; ++mt) {
            uint32_t off = arow + (uint32_t)(mt * 2048 + ks * 32) + acol;
            off ^= (off >> 3) & 0x70;
            ldsm_x4(af[mt][0], af[mt][1], af[mt][2], af[mt][3], smA + off);
        }
        uint32_t bf[8][2];
        #pragma unroll
        for (int p2 = 0; p2 < 4; ++p2) {
            uint32_t off = (uint32_t)(brow0 + p2 * 16) * 128
                         + (uint32_t)(ks * 32) + bcol;
            off ^= (off >> 3) & 0x70;
            ldsm_x4(bf[p2*2][0], bf[p2*2][1], bf[p2*2+1][0], bf[p2*2+1][1],
                    smB + off);
        }
        #pragma unroll
        for (int nt = 0; nt < 8; ++nt)
            #pragma unroll
            for (int mt = 0; mt < 4; ++mt)
                mma16816(acc[mt][nt], af[mt][0], af[mt][1], af[mt][2],
                         af[mt][3], bf[nt][0], bf[nt][1]);
    }
}

__device__ __forceinline__ void mma_mainloop(
    const char* __restrict__ A, const char* __restrict__ B,
    int K, int ld_bytes, uint32_t sm32, float acc[4][8][4])
{
    const int NC = K >> 6;
    const int tid  = threadIdx.x;
    const int lane = tid & 31;
    const int wid  = tid >> 5;
    const int wm   = wid & 1;
    const int wn   = (wid >> 1) & 1;
    const int kh   = wid >> 2;

    #pragma unroll
    for (int mt = 0; mt < 4; ++mt)
        #pragma unroll
        for (int nt = 0; nt < 8; ++nt)
            #pragma unroll
            for (int q = 0; q < 4; ++q) acc[mt][nt][q] = 0.f;

    issue_chunk(A, B, ld_bytes, 0, sm32, tid); cp_commit();
    if (NC > 1) issue_chunk(A, B, ld_bytes, 128, sm32 + STG, tid);
    cp_commit();

    int s_cur = 0, s_nxt = 2;   // stage indices mod 3
    for (int c = 0; c < NC; ++c) {
        cp_wait<1>();
        __syncthreads();
        if (c + 2 < NC)
            issue_chunk(A, B, ld_bytes, (c + 2) * 128,
                        sm32 + (uint32_t)s_nxt * STG, tid);
        cp_commit();
        uint32_t base = sm32 + (uint32_t)s_cur * STG;
        compute_chunk(base, base + 16384, lane, wm, wn, kh, acc);
        s_cur = (s_cur == 2) ? 0 : s_cur + 1;
        s_nxt = (s_nxt == 2) ? 0 : s_nxt + 1;
    }
}

// merge split-ks partials: warps 4-7 dump, warps 0-3 add. Reuses stage smem.
__device__ __forceinline__ void merge_acc(char* sm, int wid, int lane,
                                          float acc[4][8][4])
{
    float4* a4 = reinterpret_cast<float4*>(acc);
    __syncthreads();                       // mainloop done; smem reusable
    if (wid >= 4) {
        float4* mg = reinterpret_cast<float4*>(sm + (wid - 4) * 16384);
        #pragma unroll
        for (int i = 0; i < 32; ++i) mg[i * 32 + lane] = a4[i];
    }
    __syncthreads();
    if (wid < 4) {
        const float4* mg = reinterpret_cast<const float4*>(sm + wid * 16384);
        #pragma unroll
        for (int i = 0; i < 32; ++i) {
            float4 v = mg[i * 32 + lane];
            a4[i].x += v.x; a4[i].y += v.y; a4[i].z += v.z; a4[i].w += v.w;
        }
    }
}

// ---------------- phase 1: right linears (fp16) ------------------------------
__global__ void __launch_bounds__(256, 1) k_lin_r()
{
    GA_TABLES
    extern __shared__ char dsm[];
    char* sm = reinterpret_cast<char*>(((uintptr_t)dsm + 1023) & ~(uintptr_t)1023);
    uint32_t sm32 = smem_u32(sm);

    int z = blockIdx.z;
    const char* A = reinterpret_cast<const char*>(
        g_xh + (size_t)z * 262144 + (size_t)blockIdx.y * 128 * 256);
    const char* B = reinterpret_cast<const char*>(
        g_wrh + (size_t)T_GR[z] * 65536 + (size_t)blockIdx.x * 128 * 256);

    float acc[4][8][4];
    mma_mainloop(A, B, 256, 512, sm32, acc);

    int lane = threadIdx.x & 31, wid = threadIdx.x >> 5;
    merge_acc(sm, wid, lane, acc);
    if (wid < 4) {
        int wm = wid & 1, wn = (wid >> 1) & 1;
        int g4 = lane >> 2, l2 = (lane & 3) * 2;
        float* C = g_xr + (size_t)z * QP;
        int rbase = blockIdx.y * 128 + wm * 64;
        int cbase = blockIdx.x * 128 + wn * 64;
        #pragma unroll
        for (int mt = 0; mt < 4; ++mt)
            #pragma unroll
            for (int nt = 0; nt < 8; ++nt) {
                int r = rbase + mt * 16 + g4;
                int cc = cbase + nt * 8 + l2;
                *reinterpret_cast<float2*>(C + (size_t)r * 256 + cc) =
                    make_float2(acc[mt][nt][0], acc[mt][nt][1]);
                *reinterpret_cast<float2*>(C + (size_t)(r + 8) * 256 + cc) =
                    make_float2(acc[mt][nt][2], acc[mt][nt][3]);
            }
    }
}

// ---------------- normalize + build fp16 U (with x extension) ----------------
__global__ void k_build_U(const float* __restrict__ x, const float* __restrict__ norm_a)
{
    GA_TABLES
    int t = blockIdx.x * 256 + threadIdx.x;   // t = b*256 + n
    int n = t & 255, b = t >> 8;

    float xv[8];
    {
        const float4* xp = reinterpret_cast<const float4*>(x + (size_t)t * 8);
        float4 v0 = xp[0], v1 = xp[1];
        xv[0]=v0.x; xv[1]=v0.y; xv[2]=v0.z; xv[3]=v0.w;
        xv[4]=v1.x; xv[5]=v1.y; xv[6]=v1.z; xv[7]=v1.w;
    }
    float xr[8];
    #pragma unroll
    for (int i = 0; i < 8; ++i) xr[i] = g_xr[i * QP + t];

    float ngr[4];
    ngr[0] = sqrtf(xr[0]*xr[0]);
    ngr[1] = sqrtf(xr[1]*xr[1] + xr[2]*xr[2] + xr[3]*xr[3]);
    ngr[2] = sqrtf(xr[4]*xr[4] + xr[5]*xr[5] + xr[6]*xr[6]);
    ngr[3] = sqrtf(xr[7]*xr[7]);
    float inv[4];
    #pragma unroll
    for (int g = 0; g < 4; ++g) {
        float a   = norm_a[n * 4 + g];
        float sig = 1.f / (1.f + expf(-a));
        inv[g] = 1.f / (sig * (ngr[g] - 1.f) + 1.f + 1e-6f);
    }
    #pragma unroll
    for (int i = 0; i < 8; ++i) xr[i] *= inv[T_GR[i]];

    float u[8][6];
    #pragma unroll
    for (int a = 0; a < 8; ++a)
        #pragma unroll
        for (int p = 0; p < 6; ++p) u[a][p] = 0.f;

    #pragma unroll
    for (int i = 0; i < 8; ++i) {
        #pragma unroll
        for (int k = 0; k < 8; ++k) {
            int jc = T_RES[i][k];
            int pl = T_PLOC[T_GR[i]][T_GR[jc]][T_GR[k]];
            u[jc][pl] += T_SGN[i][k] * xv[i] * xr[k];
        }
    }

    #pragma unroll
    for (int jc = 0; jc < 8; ++jc) {
        int g  = T_GR[jc];
        int np = T_NP[g];
        int ld = T_LDH[g];
        long rowbase = T_UOFFX[g] + (long)(T_JLOC[jc] * 1024 + b) * ld;
        __half* dst = g_Uh + rowbase + (long)n * np;
        if (np == 4) {
            uint2 v;
            v.x = pack_h2(u[jc][0], u[jc][1]);
            v.y = pack_h2(u[jc][2], u[jc][3]);
            *reinterpret_cast<uint2*>(dst) = v;
        } else {
            uint32_t* d32 = reinterpret_cast<uint32_t*>(dst);
            d32[0] = pack_h2(u[jc][0], u[jc][1]);
            d32[1] = pack_h2(u[jc][2], u[jc][3]);
            d32[2] = pack_h2(u[jc][4], u[jc][5]);
        }
        // A extension: x component for left-linear fusion
        g_Uh[rowbase + 256 * np + n] = __float2half(xv[jc]);
    }
}

// ---------------- phase 2: grouped GEMMs -> final output ---------------------
// 128 CTAs: bid 0..47 grade1, 48..95 grade2, 96..111 grade0, 112..127 grade3
// Epilogue writes out[(b*256+mo)*8 + jc] = (acc + bias_{jc==0}) * rsqrt2.
__global__ void __launch_bounds__(256, 1) k_fused(
    const float* __restrict__ b_left, float* __restrict__ out)
{
    GA_TABLES
    extern __shared__ char dsm[];
    char* sm = reinterpret_cast<char*>(((uintptr_t)dsm + 1023) & ~(uintptr_t)1023);
    uint32_t sm32 = smem_u32(sm);

    int bid = blockIdx.x;
    int g, la;
    if      (bid <  48) { g = 1; la = bid;       }
    else if (bid <  96) { g = 2; la = bid -  48; }
    else if (bid < 112) { g = 0; la = bid -  96; }
    else                { g = 3; la = bid - 112; }
    int ly = la >> 1, col = la & 1;
    int K  = T_LDH[g];

    const char* A = reinterpret_cast<const char*>(
        g_Uh + T_UOFFX[g] + (size_t)ly * 128 * K);
    const char* B = reinterpret_cast<const char*>(
        g_wgh + T_WOFFX[g] + (size_t)col * 128 * K);

    float acc[4][8][4];
    mma_mainloop(A, B, K, K * 2, sm32, acc);

    int lane = threadIdx.x & 31, wid = threadIdx.x >> 5;
    merge_acc(sm, wid, lane, acc);
    if (wid < 4) {
        int wm = wid & 1, wn = (wid >> 1) & 1;
        int g4 = lane >> 2, l2 = (lane & 3) * 2;
        int rbase = ly * 128 + wm * 64;
        int cbase = col * 128 + wn * 64;
        #pragma unroll
        for (int mt = 0; mt < 4; ++mt)
            #pragma unroll
            for (int nt = 0; nt < 8; ++nt) {
                int cc = cbase + nt * 8 + l2;
                float bias0 = 0.f, bias1 = 0.f;
                if (g == 0) { bias0 = b_left[cc]; bias1 = b_left[cc + 1]; }
                #pragma unroll
                for (int hh = 0; hh < 2; ++hh) {
                    int r  = rbase + mt * 16 + g4 + hh * 8;
                    int jc = T_JBASE[g] + (r >> 10);
                    int bb = r & 1023;
                    float v0 = (acc[mt][nt][hh * 2]     + bias0) * RSQRT2;
                    float v1 = (acc[mt][nt][hh * 2 + 1] + bias1) * RSQRT2;
                    size_t base = ((size_t)bb * 256 + cc) * 8 + jc;
                    out[base]     = v0;
                    out[base + 8] = v1;
                }
            }
    }
}

// ---------------- launch -----------------------------------------------------
#define DSMEM_BYTES (3 * 32768 + 1024)

extern "C" void kernel_launch(void* const* d_in, const int* in_sizes, int n_in,
                              void* d_out, int out_size)
{
    const float* x   = (const float*)d_in[0];
    const float* wr  = (const float*)d_in[1];
    const float* wl  = (const float*)d_in[2];
    const float* bl  = (const float*)d_in[3];
    const float* na  = (const float*)d_in[4];
    const float* gpw = (const float*)d_in[5];
    float* out = (float*)d_out;

    cudaFuncSetAttribute(k_lin_r, cudaFuncAttributeMaxDynamicSharedMemorySize, DSMEM_BYTES);
    cudaFuncSetAttribute(k_fused, cudaFuncAttributeMaxDynamicSharedMemorySize, DSMEM_BYTES);

    k_prep<<<1536, 256>>>(x, wr, wl, gpw);

    k_lin_r<<<dim3(2, 8, 8), 256, DSMEM_BYTES>>>();

    k_build_U<<<1024, 256>>>(x, na);

    k_fused<<<128, 256, DSMEM_BYTES>>>(bl, out);
}

// round 16
// speedup vs baseline: 1.0901x; 1.0901x over previous
#include <cuda_runtime.h>
#include <cuda_fp16.h>
#include <math.h>
#include <stdint.h>

// ============================================================================
// FullyConnectedSteerableGeometricProductLayer — Cl(3,0)
// R15 = best-of-measured recomposition:
//   k_prep / k_lin_r (256-thr split-ks) / k_build_U / k_combine from R11 (fastest
//   non-fused side, 22.4us) + k_fused from R9 (128-thr, 4 warps of 64x64,
//   3-stage cp.async, 28.5us). Left linear fused into grouped GEMM via K-ext.
// ============================================================================

#define QP (1024 * 256)
#define RSQRT2 0.70710678118654752440f

// ---------------- device scratch (static; no allocations) -------------------
__device__ float g_xr  [8 * QP];           // x_right raw planes [comp][b][n]
__device__ float g_prod[8 * QP];           // (gp product + left) planes

__device__ __half g_xh [2097152];          // [comp][1024 b][256]
__device__ __half g_wrh[262144];           // [grade][256 n'][256]
// grouped B: per grade [256 mo][256*np paths | 256 w_left]
__device__ __half g_wgh[1572864];
// grouped A: per grade [(jl,b)][256*np U | 256 x]
__device__ __half g_Uh [13631488];

// ---------------- compile-time GA tables ------------------------------------
#define GA_TABLES \
  constexpr int   T_GR[8]     = {0,1,1,1,2,2,2,3};                       \
  constexpr int   T_RES[8][8] = {                                        \
    {0,1,2,3,4,5,6,7},{1,0,4,5,2,3,7,6},{2,4,0,6,1,7,3,5},               \
    {3,5,6,0,7,1,2,4},{4,2,1,7,0,6,5,3},{5,3,7,1,6,0,4,2},               \
    {6,7,3,2,5,4,0,1},{7,6,5,4,3,2,1,0}};                                \
  constexpr float T_SGN[8][8] = {                                        \
    { 1.f, 1.f, 1.f, 1.f, 1.f, 1.f, 1.f, 1.f},                           \
    { 1.f, 1.f, 1.f, 1.f, 1.f, 1.f, 1.f, 1.f},                           \
    { 1.f,-1.f, 1.f, 1.f,-1.f,-1.f, 1.f,-1.f},                           \
    { 1.f,-1.f,-1.f, 1.f, 1.f,-1.f,-1.f, 1.f},                           \
    { 1.f,-1.f, 1.f, 1.f,-1.f,-1.f, 1.f,-1.f},                           \
    { 1.f,-1.f,-1.f, 1.f, 1.f,-1.f,-1.f, 1.f},                           \
    { 1.f, 1.f,-1.f, 1.f,-1.f, 1.f,-1.f,-1.f},                           \
    { 1.f, 1.f,-1.f, 1.f,-1.f, 1.f,-1.f,-1.f}};                          \
  constexpr int   T_PLOC[4][4][4] = {                                    \
    { { 0,-1,-1,-1},{-1, 0,-1,-1},{-1,-1, 0,-1},{-1,-1,-1, 0} },         \
    { {-1, 1,-1,-1},{ 1,-1, 2,-1},{-1, 1,-1, 2},{-1,-1, 1,-1} },         \
    { {-1,-1, 2,-1},{-1, 3,-1, 4},{ 3,-1, 4,-1},{-1, 2,-1,-1} },         \
    { {-1,-1,-1, 3},{-1,-1, 5,-1},{-1, 5,-1,-1},{ 3,-1,-1,-1} } };       \
  constexpr int   T_NP[4]    = {4,6,6,4};                                \
  constexpr int   T_JLOC[8]  = {0,0,1,2,0,1,2,0};                        \
  constexpr int   T_JBASE[4] = {0,1,4,7};                                \
  constexpr int   T_LDH[4]   = {1280,1792,1792,1280};                    \
  constexpr long  T_UOFFX[4] = {0L, 1310720L, 6815744L, 12320768L};      \
  constexpr long  T_WOFFX[4] = {0L,  327680L,  786432L,  1245184L};      \
  constexpr int   T_GLOBALP[4][6] = {                                    \
    {0,4,10,16,0,0},{1,5,6,11,12,17},{2,7,8,13,14,18},{3,9,15,19,0,0} };

// ---------------- PTX helpers ------------------------------------------------
__device__ __forceinline__ uint32_t smem_u32(const void* p) {
    uint32_t a;
    asm("{ .reg .u64 t; cvta.to.shared.u64 t, %1; cvt.u32.u64 %0, t; }"
        : "=r"(a) : "l"(p));
    return a;
}
__device__ __forceinline__ void cp16(uint32_t dst, const void* src) {
    asm volatile("cp.async.cg.shared.global [%0], [%1], 16;"
                 :: "r"(dst), "l"(src));
}
__device__ __forceinline__ void cp_commit() {
    asm volatile("cp.async.commit_group;" ::: "memory");
}
template<int N>
__device__ __forceinline__ void cp_wait() {
    asm volatile("cp.async.wait_group %0;" :: "n"(N) : "memory");
}
__device__ __forceinline__ void ldsm_x4(uint32_t& r0, uint32_t& r1,
                                        uint32_t& r2, uint32_t& r3, uint32_t a) {
    asm volatile("ldmatrix.sync.aligned.m8n8.x4.shared.b16 {%0,%1,%2,%3}, [%4];"
                 : "=r"(r0), "=r"(r1), "=r"(r2), "=r"(r3) : "r"(a));
}
__device__ __forceinline__ void mma16816(float* c, uint32_t a0, uint32_t a1,
                                         uint32_t a2, uint32_t a3,
                                         uint32_t b0, uint32_t b1) {
    asm volatile("mma.sync.aligned.m16n8k16.row.col.f32.f16.f16.f32 "
                 "{%0,%1,%2,%3}, {%4,%5,%6,%7}, {%8,%9}, {%0,%1,%2,%3};"
                 : "+f"(c[0]), "+f"(c[1]), "+f"(c[2]), "+f"(c[3])
                 : "r"(a0), "r"(a1), "r"(a2), "r"(a3), "r"(b0), "r"(b1));
}
__device__ __forceinline__ uint32_t pack_h2(float a, float b) {
    __half2 h = __floats2half2_rn(a, b);
    return *reinterpret_cast<uint32_t*>(&h);
}

// ---------------- merged prep kernel -----------------------------------------
__global__ void k_prep(const float* __restrict__ x, const float* __restrict__ wr,
                       const float* __restrict__ wl, const float* __restrict__ gpw)
{
    GA_TABLES
    int blk = blockIdx.x;
    if (blk < 1024) {                                   // ---- x -> fp16
        int t = blk * 256 + threadIdx.x;                // t = b*256 + m
        int b = t >> 8, m = t & 255;
        const float4* xp = reinterpret_cast<const float4*>(x + (size_t)t * 8);
        float4 v0 = xp[0], v1 = xp[1];
        float xv[8] = {v0.x, v0.y, v0.z, v0.w, v1.x, v1.y, v1.z, v1.w};
        #pragma unroll
        for (int i = 0; i < 8; ++i)
            g_xh[(size_t)i * 262144 + (size_t)b * 256 + m] = __float2half(xv[i]);
    } else if (blk < 1280) {                            // ---- w_right / w_left(ext)
        int t = (blk - 1024) * 256 + threadIdx.x;       // t = row*256 + k
        int n = t >> 8, m = t & 255;
        float4 a = reinterpret_cast<const float4*>(wr)[t];
        float4 c = reinterpret_cast<const float4*>(wl)[t];
        float av[4] = {a.x, a.y, a.z, a.w};
        float cv[4] = {c.x, c.y, c.z, c.w};
        #pragma unroll
        for (int g = 0; g < 4; ++g) {
            g_wrh[(size_t)g * 65536 + (size_t)n * 256 + m] = __float2half(av[g]);
            g_wgh[T_WOFFX[g] + (size_t)n * T_LDH[g] + 256 * T_NP[g] + m] =
                __float2half(cv[g]);
        }
    } else {                                            // ---- gp path weights
        int t  = (blk - 1280) * 256 + threadIdx.x;      // t = mo*256 + n
        int mo = t >> 8, n = t & 255;
        float w[20];
        const float4* p4 = reinterpret_cast<const float4*>(gpw + (size_t)t * 20);
        #pragma unroll
        for (int q = 0; q < 5; ++q) {
            float4 v = p4[q];
            w[q*4+0] = v.x; w[q*4+1] = v.y; w[q*4+2] = v.z; w[q*4+3] = v.w;
        }
        #pragma unroll
        for (int g = 0; g < 4; ++g) {
            int np = T_NP[g];
            long base = T_WOFFX[g] + (long)mo * T_LDH[g] + (long)n * np;
            #pragma unroll
            for (int pl = 0; pl < 6; ++pl)
                if (pl < np) g_wgh[base + pl] = __float2half(w[T_GLOBALP[g][pl]]);
        }
    }
}

// ---------------- shared GEMM building blocks --------------------------------
// C(128x128) = A(128 x K) * B^T. Chunk = 64 fp16 of K (128B rows, SW128).
// Stage = 32KB (A 16KB @0 + B 16KB @16384).
#define STG 32768

template<int NT>
__device__ __forceinline__ void issue_chunk(
    const char* __restrict__ A, const char* __restrict__ B,
    int ld_bytes, int koff_b, uint32_t dst, int tid)
{
    #pragma unroll
    for (int j = 0; j < 1024 / NT; ++j) {
        int idx = tid + j * NT;
        int row = idx >> 3, c16 = idx & 7;
        uint32_t off = (uint32_t)(row * 128 + c16 * 16);
        off ^= (off >> 3) & 0x70;
        cp16(dst + off, A + (size_t)row * ld_bytes + koff_b + c16 * 16);
    }
    #pragma unroll
    for (int j = 0; j < 1024 / NT; ++j) {
        int idx = tid + j * NT;
        int row = idx >> 3, c16 = idx & 7;
        uint32_t off = (uint32_t)(row * 128 + c16 * 16);
        off ^= (off >> 3) & 0x70;
        cp16(dst + 16384 + off, B + (size_t)row * ld_bytes + koff_b + c16 * 16);
    }
}

// warp tile 64x64: mt=4 (16-row), nt=8 (8-col); wm,wn in {0,1}; ks in [ks0,ksn)
__device__ __forceinline__ void compute_chunk(
    uint32_t smA, uint32_t smB, int lane, int wm, int wn, int ks0, int ksn,
    float acc[4][8][4])
{
    const uint32_t arow = (uint32_t)(wm * 64 + (lane & 15)) * 128;
    const uint32_t acol = ((lane >> 4) & 1) * 16;
    const int bm = lane >> 3, br = lane & 7;
    const uint32_t bcol = (uint32_t)(bm & 1) * 16;
    const int brow0 = wn * 64 + (bm >> 1) * 8 + br;
    for (int ks = ks0; ks < ksn; ++ks) {
        uint32_t af[4][4];
        #pragma unroll
        for (int mt = 0; mt < 4; ++mt) {
            uint32_t off = arow + (uint32_t)(mt * 2048 + ks * 32) + acol;
            off ^= (off >> 3) & 0x70;
            ldsm_x4(af[mt][0], af[mt][1], af[mt][2], af[mt][3], smA + off);
        }
        uint32_t bf[8][2];
        #pragma unroll
        for (int p2 = 0; p2 < 4; ++p2) {
            uint32_t off = (uint32_t)(brow0 + p2 * 16) * 128
                         + (uint32_t)(ks * 32) + bcol;
            off ^= (off >> 3) & 0x70;
            ldsm_x4(bf[p2*2][0], bf[p2*2][1], bf[p2*2+1][0], bf[p2*2+1][1],
                    smB + off);
        }
        #pragma unroll
        for (int nt = 0; nt < 8; ++nt)
            #pragma unroll
            for (int mt = 0; mt < 4; ++mt)
                mma16816(acc[mt][nt], af[mt][0], af[mt][1], af[mt][2],
                         af[mt][3], bf[nt][0], bf[nt][1]);
    }
}

// NT=128: 4 warps, each full 64x64 tile, all 4 ks.
// NT=256: 8 warps, split-ks (warps 0-3: ks{0,1}; 4-7: ks{2,3}), merge later.
template<int NT>
__device__ __forceinline__ void mma_mainloop(
    const char* __restrict__ A, const char* __restrict__ B,
    int K, int ld_bytes, uint32_t sm32, float acc[4][8][4])
{
    const int NC = K >> 6;
    const int tid  = threadIdx.x;
    const int lane = tid & 31;
    const int wid  = tid >> 5;
    const int wm   = wid & 1;
    const int wn   = (NT == 128) ? (wid >> 1) : ((wid >> 1) & 1);
    const int ks0  = (NT == 128) ? 0 : (wid >> 2) * 2;
    const int ksn  = (NT == 128) ? 4 : ks0 + 2;

    #pragma unroll
    for (int mt = 0; mt < 4; ++mt)
        #pragma unroll
        for (int nt = 0; nt < 8; ++nt)
            #pragma unroll
            for (int q = 0; q < 4; ++q) acc[mt][nt][q] = 0.f;

    issue_chunk<NT>(A, B, ld_bytes, 0, sm32, tid); cp_commit();
    if (NC > 1) issue_chunk<NT>(A, B, ld_bytes, 128, sm32 + STG, tid);
    cp_commit();

    int s_cur = 0, s_nxt = 2;   // stage indices mod 3
    for (int c = 0; c < NC; ++c) {
        cp_wait<1>();
        __syncthreads();
        if (c + 2 < NC)
            issue_chunk<NT>(A, B, ld_bytes, (c + 2) * 128,
                            sm32 + (uint32_t)s_nxt * STG, tid);
        cp_commit();
        uint32_t base = sm32 + (uint32_t)s_cur * STG;
        compute_chunk(base, base + 16384, lane, wm, wn, ks0, ksn, acc);
        s_cur = (s_cur == 2) ? 0 : s_cur + 1;
        s_nxt = (s_nxt == 2) ? 0 : s_nxt + 1;
    }
}

// merge split-ks partials (NT=256): warps 4-7 dump, warps 0-3 add.
__device__ __forceinline__ void merge_acc(char* sm, int wid, int lane,
                                          float acc[4][8][4])
{
    float4* a4 = reinterpret_cast<float4*>(acc);
    __syncthreads();                       // mainloop done; smem reusable
    if (wid >= 4) {
        float4* mg = reinterpret_cast<float4*>(sm + (wid - 4) * 16384);
        #pragma unroll
        for (int i = 0; i < 32; ++i) mg[i * 32 + lane] = a4[i];
    }
    __syncthreads();
    if (wid < 4) {
        const float4* mg = reinterpret_cast<const float4*>(sm + wid * 16384);
        #pragma unroll
        for (int i = 0; i < 32; ++i) {
            float4 v = mg[i * 32 + lane];
            a4[i].x += v.x; a4[i].y += v.y; a4[i].z += v.z; a4[i].w += v.w;
        }
    }
}

// ---------------- phase 1: right linears (256 thr, split-ks) -----------------
__global__ void __launch_bounds__(256, 1) k_lin_r()
{
    GA_TABLES
    extern __shared__ char dsm[];
    char* sm = reinterpret_cast<char*>(((uintptr_t)dsm + 1023) & ~(uintptr_t)1023);
    uint32_t sm32 = smem_u32(sm);

    int z = blockIdx.z;
    const char* A = reinterpret_cast<const char*>(
        g_xh + (size_t)z * 262144 + (size_t)blockIdx.y * 128 * 256);
    const char* B = reinterpret_cast<const char*>(
        g_wrh + (size_t)T_GR[z] * 65536 + (size_t)blockIdx.x * 128 * 256);

    float acc[4][8][4];
    mma_mainloop<256>(A, B, 256, 512, sm32, acc);

    int lane = threadIdx.x & 31, wid = threadIdx.x >> 5;
    merge_acc(sm, wid, lane, acc);
    if (wid < 4) {
        int wm = wid & 1, wn = (wid >> 1) & 1;
        int g4 = lane >> 2, l2 = (lane & 3) * 2;
        float* C = g_xr + (size_t)z * QP;
        int rbase = blockIdx.y * 128 + wm * 64;
        int cbase = blockIdx.x * 128 + wn * 64;
        #pragma unroll
        for (int mt = 0; mt < 4; ++mt)
            #pragma unroll
            for (int nt = 0; nt < 8; ++nt) {
                int r = rbase + mt * 16 + g4;
                int cc = cbase + nt * 8 + l2;
                *reinterpret_cast<float2*>(C + (size_t)r * 256 + cc) =
                    make_float2(acc[mt][nt][0], acc[mt][nt][1]);
                *reinterpret_cast<float2*>(C + (size_t)(r + 8) * 256 + cc) =
                    make_float2(acc[mt][nt][2], acc[mt][nt][3]);
            }
    }
}

// ---------------- normalize + build fp16 U (with x extension) ----------------
__global__ void k_build_U(const float* __restrict__ x, const float* __restrict__ norm_a)
{
    GA_TABLES
    int t = blockIdx.x * 256 + threadIdx.x;   // t = b*256 + n
    int n = t & 255, b = t >> 8;

    float xv[8];
    {
        const float4* xp = reinterpret_cast<const float4*>(x + (size_t)t * 8);
        float4 v0 = xp[0], v1 = xp[1];
        xv[0]=v0.x; xv[1]=v0.y; xv[2]=v0.z; xv[3]=v0.w;
        xv[4]=v1.x; xv[5]=v1.y; xv[6]=v1.z; xv[7]=v1.w;
    }
    float xr[8];
    #pragma unroll
    for (int i = 0; i < 8; ++i) xr[i] = g_xr[i * QP + t];

    float ngr[4];
    ngr[0] = sqrtf(xr[0]*xr[0]);
    ngr[1] = sqrtf(xr[1]*xr[1] + xr[2]*xr[2] + xr[3]*xr[3]);
    ngr[2] = sqrtf(xr[4]*xr[4] + xr[5]*xr[5] + xr[6]*xr[6]);
    ngr[3] = sqrtf(xr[7]*xr[7]);
    float inv[4];
    #pragma unroll
    for (int g = 0; g < 4; ++g) {
        float a   = norm_a[n * 4 + g];
        float sig = 1.f / (1.f + expf(-a));
        inv[g] = 1.f / (sig * (ngr[g] - 1.f) + 1.f + 1e-6f);
    }
    #pragma unroll
    for (int i = 0; i < 8; ++i) xr[i] *= inv[T_GR[i]];

    float u[8][6];
    #pragma unroll
    for (int a = 0; a < 8; ++a)
        #pragma unroll
        for (int p = 0; p < 6; ++p) u[a][p] = 0.f;

    #pragma unroll
    for (int i = 0; i < 8; ++i) {
        #pragma unroll
        for (int k = 0; k < 8; ++k) {
            int jc = T_RES[i][k];
            int pl = T_PLOC[T_GR[i]][T_GR[jc]][T_GR[k]];
            u[jc][pl] += T_SGN[i][k] * xv[i] * xr[k];
        }
    }

    #pragma unroll
    for (int jc = 0; jc < 8; ++jc) {
        int g  = T_GR[jc];
        int np = T_NP[g];
        int ld = T_LDH[g];
        long rowbase = T_UOFFX[g] + (long)(T_JLOC[jc] * 1024 + b) * ld;
        __half* dst = g_Uh + rowbase + (long)n * np;
        if (np == 4) {
            uint2 v;
            v.x = pack_h2(u[jc][0], u[jc][1]);
            v.y = pack_h2(u[jc][2], u[jc][3]);
            *reinterpret_cast<uint2*>(dst) = v;
        } else {
            uint32_t* d32 = reinterpret_cast<uint32_t*>(dst);
            d32[0] = pack_h2(u[jc][0], u[jc][1]);
            d32[1] = pack_h2(u[jc][2], u[jc][3]);
            d32[2] = pack_h2(u[jc][4], u[jc][5]);
        }
        // A extension: x component for left-linear fusion
        g_Uh[rowbase + 256 * np + n] = __float2half(xv[jc]);
    }
}

// ---------------- phase 2: grouped GEMMs (128 thr, R9 config) ----------------
// 128 CTAs: bid 0..47 grade1, 48..95 grade2, 96..111 grade0, 112..127 grade3
__global__ void __launch_bounds__(128, 2) k_fused()
{
    GA_TABLES
    extern __shared__ char dsm[];
    char* sm = reinterpret_cast<char*>(((uintptr_t)dsm + 1023) & ~(uintptr_t)1023);
    uint32_t sm32 = smem_u32(sm);

    int bid = blockIdx.x;
    int g, la;
    if      (bid <  48) { g = 1; la = bid;       }
    else if (bid <  96) { g = 2; la = bid -  48; }
    else if (bid < 112) { g = 0; la = bid -  96; }
    else                { g = 3; la = bid - 112; }
    int ly = la >> 1, col = la & 1;
    int K  = T_LDH[g];

    const char* A = reinterpret_cast<const char*>(
        g_Uh + T_UOFFX[g] + (size_t)ly * 128 * K);
    const char* B = reinterpret_cast<const char*>(
        g_wgh + T_WOFFX[g] + (size_t)col * 128 * K);

    float acc[4][8][4];
    mma_mainloop<128>(A, B, K, K * 2, sm32, acc);

    int lane = threadIdx.x & 31, wid = threadIdx.x >> 5;
    int wm = wid & 1, wn = wid >> 1;
    int g4 = lane >> 2, l2 = (lane & 3) * 2;
    int rbase = ly * 128 + wm * 64;
    int cbase = col * 128 + wn * 32 * 2;   // wn in {0,1}: 64-col halves
    #pragma unroll
    for (int mt = 0; mt < 4; ++mt)
        #pragma unroll
        for (int nt = 0; nt < 8; ++nt) {
            int r0 = rbase + mt * 16 + g4;
            int cc = cbase + nt * 8 + l2;
            #pragma unroll
            for (int hh = 0; hh < 2; ++hh) {
                int r  = r0 + hh * 8;
                int jc = T_JBASE[g] + (r >> 10);
                int bb = r & 1023;
                *reinterpret_cast<float2*>(
                    g_prod + (size_t)jc * QP + (size_t)bb * 256 + cc) =
                    make_float2(acc[mt][nt][hh * 2], acc[mt][nt][hh * 2 + 1]);
            }
        }
}

// ---------------- final combine ----------------------------------------------
__global__ void k_combine(const float* __restrict__ b_left, float* __restrict__ out)
{
    int t = blockIdx.x * 256 + threadIdx.x;   // t = b*256 + mo
    int m = t & 255;
    float o[8];
    #pragma unroll
    for (int j = 0; j < 8; ++j) {
        float v = g_prod[j * QP + t];
        if (j == 0) v += b_left[m];
        o[j] = v * RSQRT2;
    }
    float4* op = reinterpret_cast<float4*>(out + (size_t)t * 8);
    op[0] = make_float4(o[0], o[1], o[2], o[3]);
    op[1] = make_float4(o[4], o[5], o[6], o[7]);
}

// ---------------- launch -----------------------------------------------------
#define DSMEM_BYTES (3 * 32768 + 1024)

extern "C" void kernel_launch(void* const* d_in, const int* in_sizes, int n_in,
                              void* d_out, int out_size)
{
    const float* x   = (const float*)d_in[0];
    const float* wr  = (const float*)d_in[1];
    const float* wl  = (const float*)d_in[2];
    const float* bl  = (const float*)d_in[3];
    const float* na  = (const float*)d_in[4];
    const float* gpw = (const float*)d_in[5];
    float* out = (float*)d_out;

    cudaFuncSetAttribute(k_lin_r, cudaFuncAttributeMaxDynamicSharedMemorySize, DSMEM_BYTES);
    cudaFuncSetAttribute(k_fused, cudaFuncAttributeMaxDynamicSharedMemorySize, DSMEM_BYTES);

    k_prep<<<1536, 256>>>(x, wr, wl, gpw);

    k_lin_r<<<dim3(2, 8, 8), 256, DSMEM_BYTES>>>();

    k_build_U<<<1024, 256>>>(x, na);

    k_fused<<<128, 128, DSMEM_BYTES>>>();

    k_combine<<<1024, 256>>>(bl, out);
}

// round 17
// speedup vs baseline: 1.1121x; 1.0202x over previous
#include <cuda_runtime.h>
#include <cuda_fp16.h>
#include <math.h>
#include <stdint.h>

// ============================================================================
// FullyConnectedSteerableGeometricProductLayer — Cl(3,0)
// R16 = R15 (best, 53.3us) + gpw-prep merged into lin_r launch (fills the
//   20 idle SMs during lin_r), prep shrunk to x+w only.
//   GEMMs at the measured sm_103 mma.sync ceiling (~512 MAC/cyc/SM).
// ============================================================================

#define QP (1024 * 256)
#define RSQRT2 0.70710678118654752440f

// ---------------- device scratch (static; no allocations) -------------------
__device__ float g_xr  [8 * QP];           // x_right raw planes [comp][b][n]
__device__ float g_prod[8 * QP];           // (gp product + left) planes

__device__ __half g_xh [2097152];          // [comp][1024 b][256]
__device__ __half g_wrh[262144];           // [grade][256 n'][256]
// grouped B: per grade [256 mo][256*np paths | 256 w_left]
__device__ __half g_wgh[1572864];
// grouped A: per grade [(jl,b)][256*np U | 256 x]
__device__ __half g_Uh [13631488];

// ---------------- compile-time GA tables ------------------------------------
#define GA_TABLES \
  constexpr int   T_GR[8]     = {0,1,1,1,2,2,2,3};                       \
  constexpr int   T_RES[8][8] = {                                        \
    {0,1,2,3,4,5,6,7},{1,0,4,5,2,3,7,6},{2,4,0,6,1,7,3,5},               \
    {3,5,6,0,7,1,2,4},{4,2,1,7,0,6,5,3},{5,3,7,1,6,0,4,2},               \
    {6,7,3,2,5,4,0,1},{7,6,5,4,3,2,1,0}};                                \
  constexpr float T_SGN[8][8] = {                                        \
    { 1.f, 1.f, 1.f, 1.f, 1.f, 1.f, 1.f, 1.f},                           \
    { 1.f, 1.f, 1.f, 1.f, 1.f, 1.f, 1.f, 1.f},                           \
    { 1.f,-1.f, 1.f, 1.f,-1.f,-1.f, 1.f,-1.f},                           \
    { 1.f,-1.f,-1.f, 1.f, 1.f,-1.f,-1.f, 1.f},                           \
    { 1.f,-1.f, 1.f, 1.f,-1.f,-1.f, 1.f,-1.f},                           \
    { 1.f,-1.f,-1.f, 1.f, 1.f,-1.f,-1.f, 1.f},                           \
    { 1.f, 1.f,-1.f, 1.f,-1.f, 1.f,-1.f,-1.f},                           \
    { 1.f, 1.f,-1.f, 1.f,-1.f, 1.f,-1.f,-1.f}};                          \
  constexpr int   T_PLOC[4][4][4] = {                                    \
    { { 0,-1,-1,-1},{-1, 0,-1,-1},{-1,-1, 0,-1},{-1,-1,-1, 0} },         \
    { {-1, 1,-1,-1},{ 1,-1, 2,-1},{-1, 1,-1, 2},{-1,-1, 1,-1} },         \
    { {-1,-1, 2,-1},{-1, 3,-1, 4},{ 3,-1, 4,-1},{-1, 2,-1,-1} },         \
    { {-1,-1,-1, 3},{-1,-1, 5,-1},{-1, 5,-1,-1},{ 3,-1,-1,-1} } };       \
  constexpr int   T_NP[4]    = {4,6,6,4};                                \
  constexpr int   T_JLOC[8]  = {0,0,1,2,0,1,2,0};                        \
  constexpr int   T_JBASE[4] = {0,1,4,7};                                \
  constexpr int   T_LDH[4]   = {1280,1792,1792,1280};                    \
  constexpr long  T_UOFFX[4] = {0L, 1310720L, 6815744L, 12320768L};      \
  constexpr long  T_WOFFX[4] = {0L,  327680L,  786432L,  1245184L};      \
  constexpr int   T_GLOBALP[4][6] = {                                    \
    {0,4,10,16,0,0},{1,5,6,11,12,17},{2,7,8,13,14,18},{3,9,15,19,0,0} };

// ---------------- PTX helpers ------------------------------------------------
__device__ __forceinline__ uint32_t smem_u32(const void* p) {
    uint32_t a;
    asm("{ .reg .u64 t; cvta.to.shared.u64 t, %1; cvt.u32.u64 %0, t; }"
        : "=r"(a) : "l"(p));
    return a;
}
__device__ __forceinline__ void cp16(uint32_t dst, const void* src) {
    asm volatile("cp.async.cg.shared.global [%0], [%1], 16;"
                 :: "r"(dst), "l"(src));
}
__device__ __forceinline__ void cp_commit() {
    asm volatile("cp.async.commit_group;" ::: "memory");
}
template<int N>
__device__ __forceinline__ void cp_wait() {
    asm volatile("cp.async.wait_group %0;" :: "n"(N) : "memory");
}
__device__ __forceinline__ void ldsm_x4(uint32_t& r0, uint32_t& r1,
                                        uint32_t& r2, uint32_t& r3, uint32_t a) {
    asm volatile("ldmatrix.sync.aligned.m8n8.x4.shared.b16 {%0,%1,%2,%3}, [%4];"
                 : "=r"(r0), "=r"(r1), "=r"(r2), "=r"(r3) : "r"(a));
}
__device__ __forceinline__ void mma16816(float* c, uint32_t a0, uint32_t a1,
                                         uint32_t a2, uint32_t a3,
                                         uint32_t b0, uint32_t b1) {
    asm volatile("mma.sync.aligned.m16n8k16.row.col.f32.f16.f16.f32 "
                 "{%0,%1,%2,%3}, {%4,%5,%6,%7}, {%8,%9}, {%0,%1,%2,%3};"
                 : "+f"(c[0]), "+f"(c[1]), "+f"(c[2]), "+f"(c[3])
                 : "r"(a0), "r"(a1), "r"(a2), "r"(a3), "r"(b0), "r"(b1));
}
__device__ __forceinline__ uint32_t pack_h2(float a, float b) {
    __half2 h = __floats2half2_rn(a, b);
    return *reinterpret_cast<uint32_t*>(&h);
}

// ---------------- prep kernel (x + w only) -----------------------------------
__global__ void k_prep(const float* __restrict__ x, const float* __restrict__ wr,
                       const float* __restrict__ wl)
{
    GA_TABLES
    int blk = blockIdx.x;
    if (blk < 1024) {                                   // ---- x -> fp16
        int t = blk * 256 + threadIdx.x;                // t = b*256 + m
        int b = t >> 8, m = t & 255;
        const float4* xp = reinterpret_cast<const float4*>(x + (size_t)t * 8);
        float4 v0 = xp[0], v1 = xp[1];
        float xv[8] = {v0.x, v0.y, v0.z, v0.w, v1.x, v1.y, v1.z, v1.w};
        #pragma unroll
        for (int i = 0; i < 8; ++i)
            g_xh[(size_t)i * 262144 + (size_t)b * 256 + m] = __float2half(xv[i]);
    } else {                                            // ---- w_right / w_left(ext)
        int t = (blk - 1024) * 256 + threadIdx.x;       // t = row*256 + k
        int n = t >> 8, m = t & 255;
        float4 a = reinterpret_cast<const float4*>(wr)[t];
        float4 c = reinterpret_cast<const float4*>(wl)[t];
        float av[4] = {a.x, a.y, a.z, a.w};
        float cv[4] = {c.x, c.y, c.z, c.w};
        #pragma unroll
        for (int g = 0; g < 4; ++g) {
            g_wrh[(size_t)g * 65536 + (size_t)n * 256 + m] = __float2half(av[g]);
            g_wgh[T_WOFFX[g] + (size_t)n * T_LDH[g] + 256 * T_NP[g] + m] =
                __float2half(cv[g]);
        }
    }
}

// ---------------- shared GEMM building blocks --------------------------------
// C(128x128) = A(128 x K) * B^T. Chunk = 64 fp16 of K (128B rows, SW128).
// Stage = 32KB (A 16KB @0 + B 16KB @16384).
#define STG 32768

template<int NT>
__device__ __forceinline__ void issue_chunk(
    const char* __restrict__ A, const char* __restrict__ B,
    int ld_bytes, int koff_b, uint32_t dst, int tid)
{
    #pragma unroll
    for (int j = 0; j < 1024 / NT; ++j) {
        int idx = tid + j * NT;
        int row = idx >> 3, c16 = idx & 7;
        uint32_t off = (uint32_t)(row * 128 + c16 * 16);
        off ^= (off >> 3) & 0x70;
        cp16(dst + off, A + (size_t)row * ld_bytes + koff_b + c16 * 16);
    }
    #pragma unroll
    for (int j = 0; j < 1024 / NT; ++j) {
        int idx = tid + j * NT;
        int row = idx >> 3, c16 = idx & 7;
        uint32_t off = (uint32_t)(row * 128 + c16 * 16);
        off ^= (off >> 3) & 0x70;
        cp16(dst + 16384 + off, B + (size_t)row * ld_bytes + koff_b + c16 * 16);
    }
}

// warp tile 64x64: mt=4 (16-row), nt=8 (8-col); wm,wn in {0,1}; ks in [ks0,ksn)
__device__ __forceinline__ void compute_chunk(
    uint32_t smA, uint32_t smB, int lane, int wm, int wn, int ks0, int ksn,
    float acc[4][8][4])
{
    const uint32_t arow = (uint32_t)(wm * 64 + (lane & 15)) * 128;
    const uint32_t acol = ((lane >> 4) & 1) * 16;
    const int bm = lane >> 3, br = lane & 7;
    const uint32_t bcol = (uint32_t)(bm & 1) * 16;
    const int brow0 = wn * 64 + (bm >> 1) * 8 + br;
    for (int ks = ks0; ks < ksn; ++ks) {
        uint32_t af[4][4];
        #pragma unroll
        for (int mt = 0; mt < 4; ++mt) {
            uint32_t off = arow + (uint32_t)(mt * 2048 + ks * 32) + acol;
            off ^= (off >> 3) & 0x70;
            ldsm_x4(af[mt][0], af[mt][1], af[mt][2], af[mt][3], smA + off);
        }
        uint32_t bf[8][2];
        #pragma unroll
        for (int p2 = 0; p2 < 4; ++p2) {
            uint32_t off = (uint32_t)(brow0 + p2 * 16) * 128
                         + (uint32_t)(ks * 32) + bcol;
            off ^= (off >> 3) & 0x70;
            ldsm_x4(bf[p2*2][0], bf[p2*2][1], bf[p2*2+1][0], bf[p2*2+1][1],
                    smB + off);
        }
        #pragma unroll
        for (int nt = 0; nt < 8; ++nt)
            #pragma unroll
            for (int mt = 0; mt < 4; ++mt)
                mma16816(acc[mt][nt], af[mt][0], af[mt][1], af[mt][2],
                         af[mt][3], bf[nt][0], bf[nt][1]);
    }
}

// NT=128: 4 warps, each full 64x64 tile, all 4 ks.
// NT=256: 8 warps, split-ks (warps 0-3: ks{0,1}; 4-7: ks{2,3}), merge later.
template<int NT>
__device__ __forceinline__ void mma_mainloop(
    const char* __restrict__ A, const char* __restrict__ B,
    int K, int ld_bytes, uint32_t sm32, float acc[4][8][4])
{
    const int NC = K >> 6;
    const int tid  = threadIdx.x;
    const int lane = tid & 31;
    const int wid  = tid >> 5;
    const int wm   = wid & 1;
    const int wn   = (NT == 128) ? (wid >> 1) : ((wid >> 1) & 1);
    const int ks0  = (NT == 128) ? 0 : (wid >> 2) * 2;
    const int ksn  = (NT == 128) ? 4 : ks0 + 2;

    #pragma unroll
    for (int mt = 0; mt < 4; ++mt)
        #pragma unroll
        for (int nt = 0; nt < 8; ++nt)
            #pragma unroll
            for (int q = 0; q < 4; ++q) acc[mt][nt][q] = 0.f;

    issue_chunk<NT>(A, B, ld_bytes, 0, sm32, tid); cp_commit();
    if (NC > 1) issue_chunk<NT>(A, B, ld_bytes, 128, sm32 + STG, tid);
    cp_commit();

    int s_cur = 0, s_nxt = 2;   // stage indices mod 3
    for (int c = 0; c < NC; ++c) {
        cp_wait<1>();
        __syncthreads();
        if (c + 2 < NC)
            issue_chunk<NT>(A, B, ld_bytes, (c + 2) * 128,
                            sm32 + (uint32_t)s_nxt * STG, tid);
        cp_commit();
        uint32_t base = sm32 + (uint32_t)s_cur * STG;
        compute_chunk(base, base + 16384, lane, wm, wn, ks0, ksn, acc);
        s_cur = (s_cur == 2) ? 0 : s_cur + 1;
        s_nxt = (s_nxt == 2) ? 0 : s_nxt + 1;
    }
}

// merge split-ks partials (NT=256): warps 4-7 dump, warps 0-3 add.
__device__ __forceinline__ void merge_acc(char* sm, int wid, int lane,
                                          float acc[4][8][4])
{
    float4* a4 = reinterpret_cast<float4*>(acc);
    __syncthreads();                       // mainloop done; smem reusable
    if (wid >= 4) {
        float4* mg = reinterpret_cast<float4*>(sm + (wid - 4) * 16384);
        #pragma unroll
        for (int i = 0; i < 32; ++i) mg[i * 32 + lane] = a4[i];
    }
    __syncthreads();
    if (wid < 4) {
        const float4* mg = reinterpret_cast<const float4*>(sm + wid * 16384);
        #pragma unroll
        for (int i = 0; i < 32; ++i) {
            float4 v = mg[i * 32 + lane];
            a4[i].x += v.x; a4[i].y += v.y; a4[i].z += v.z; a4[i].w += v.w;
        }
    }
}

// ---------------- phase 1: right linears + gpw prep (one launch) -------------
// 1-D grid of 384 CTAs: bid<128 = GEMM tiles (x=bid&1, y=(bid>>1)&7, z=bid>>4);
// bid>=128 = gp path-weight prep (fills the 20 idle SMs during lin_r).
__global__ void __launch_bounds__(256, 1) k_lin_r(const float* __restrict__ gpw)
{
    GA_TABLES
    int bid = blockIdx.x;
    if (bid >= 128) {                       // ---- gpw prep CTA
        int t  = (bid - 128) * 256 + threadIdx.x;   // t = mo*256 + n
        int mo = t >> 8, n = t & 255;
        float w[20];
        const float4* p4 = reinterpret_cast<const float4*>(gpw + (size_t)t * 20);
        #pragma unroll
        for (int q = 0; q < 5; ++q) {
            float4 v = p4[q];
            w[q*4+0] = v.x; w[q*4+1] = v.y; w[q*4+2] = v.z; w[q*4+3] = v.w;
        }
        #pragma unroll
        for (int g = 0; g < 4; ++g) {
            int np = T_NP[g];
            long base = T_WOFFX[g] + (long)mo * T_LDH[g] + (long)n * np;
            #pragma unroll
            for (int pl = 0; pl < 6; ++pl)
                if (pl < np) g_wgh[base + pl] = __float2half(w[T_GLOBALP[g][pl]]);
        }
        return;
    }

    extern __shared__ char dsm[];
    char* sm = reinterpret_cast<char*>(((uintptr_t)dsm + 1023) & ~(uintptr_t)1023);
    uint32_t sm32 = smem_u32(sm);

    int bx = bid & 1, by = (bid >> 1) & 7, z = bid >> 4;
    const char* A = reinterpret_cast<const char*>(
        g_xh + (size_t)z * 262144 + (size_t)by * 128 * 256);
    const char* B = reinterpret_cast<const char*>(
        g_wrh + (size_t)T_GR[z] * 65536 + (size_t)bx * 128 * 256);

    float acc[4][8][4];
    mma_mainloop<256>(A, B, 256, 512, sm32, acc);

    int lane = threadIdx.x & 31, wid = threadIdx.x >> 5;
    merge_acc(sm, wid, lane, acc);
    if (wid < 4) {
        int wm = wid & 1, wn = (wid >> 1) & 1;
        int g4 = lane >> 2, l2 = (lane & 3) * 2;
        float* C = g_xr + (size_t)z * QP;
        int rbase = by * 128 + wm * 64;
        int cbase = bx * 128 + wn * 64;
        #pragma unroll
        for (int mt = 0; mt < 4; ++mt)
            #pragma unroll
            for (int nt = 0; nt < 8; ++nt) {
                int r = rbase + mt * 16 + g4;
                int cc = cbase + nt * 8 + l2;
                *reinterpret_cast<float2*>(C + (size_t)r * 256 + cc) =
                    make_float2(acc[mt][nt][0], acc[mt][nt][1]);
                *reinterpret_cast<float2*>(C + (size_t)(r + 8) * 256 + cc) =
                    make_float2(acc[mt][nt][2], acc[mt][nt][3]);
            }
    }
}

// ---------------- normalize + build fp16 U (with x extension) ----------------
__global__ void k_build_U(const float* __restrict__ x, const float* __restrict__ norm_a)
{
    GA_TABLES
    int t = blockIdx.x * 256 + threadIdx.x;   // t = b*256 + n
    int n = t & 255, b = t >> 8;

    float xv[8];
    {
        const float4* xp = reinterpret_cast<const float4*>(x + (size_t)t * 8);
        float4 v0 = xp[0], v1 = xp[1];
        xv[0]=v0.x; xv[1]=v0.y; xv[2]=v0.z; xv[3]=v0.w;
        xv[4]=v1.x; xv[5]=v1.y; xv[6]=v1.z; xv[7]=v1.w;
    }
    float xr[8];
    #pragma unroll
    for (int i = 0; i < 8; ++i) xr[i] = g_xr[i * QP + t];

    float ngr[4];
    ngr[0] = sqrtf(xr[0]*xr[0]);
    ngr[1] = sqrtf(xr[1]*xr[1] + xr[2]*xr[2] + xr[3]*xr[3]);
    ngr[2] = sqrtf(xr[4]*xr[4] + xr[5]*xr[5] + xr[6]*xr[6]);
    ngr[3] = sqrtf(xr[7]*xr[7]);
    float inv[4];
    #pragma unroll
    for (int g = 0; g < 4; ++g) {
        float a   = norm_a[n * 4 + g];
        float sig = 1.f / (1.f + expf(-a));
        inv[g] = 1.f / (sig * (ngr[g] - 1.f) + 1.f + 1e-6f);
    }
    #pragma unroll
    for (int i = 0; i < 8; ++i) xr[i] *= inv[T_GR[i]];

    float u[8][6];
    #pragma unroll
    for (int a = 0; a < 8; ++a)
        #pragma unroll
        for (int p = 0; p < 6; ++p) u[a][p] = 0.f;

    #pragma unroll
    for (int i = 0; i < 8; ++i) {
        #pragma unroll
        for (int k = 0; k < 8; ++k) {
            int jc = T_RES[i][k];
            int pl = T_PLOC[T_GR[i]][T_GR[jc]][T_GR[k]];
            u[jc][pl] += T_SGN[i][k] * xv[i] * xr[k];
        }
    }

    #pragma unroll
    for (int jc = 0; jc < 8; ++jc) {
        int g  = T_GR[jc];
        int np = T_NP[g];
        int ld = T_LDH[g];
        long rowbase = T_UOFFX[g] + (long)(T_JLOC[jc] * 1024 + b) * ld;
        __half* dst = g_Uh + rowbase + (long)n * np;
        if (np == 4) {
            uint2 v;
            v.x = pack_h2(u[jc][0], u[jc][1]);
            v.y = pack_h2(u[jc][2], u[jc][3]);
            *reinterpret_cast<uint2*>(dst) = v;
        } else {
            uint32_t* d32 = reinterpret_cast<uint32_t*>(dst);
            d32[0] = pack_h2(u[jc][0], u[jc][1]);
            d32[1] = pack_h2(u[jc][2], u[jc][3]);
            d32[2] = pack_h2(u[jc][4], u[jc][5]);
        }
        // A extension: x component for left-linear fusion
        g_Uh[rowbase + 256 * np + n] = __float2half(xv[jc]);
    }
}

// ---------------- phase 2: grouped GEMMs (128 thr) ---------------------------
// 128 CTAs: bid 0..47 grade1, 48..95 grade2, 96..111 grade0, 112..127 grade3
__global__ void __launch_bounds__(128, 2) k_fused()
{
    GA_TABLES
    extern __shared__ char dsm[];
    char* sm = reinterpret_cast<char*>(((uintptr_t)dsm + 1023) & ~(uintptr_t)1023);
    uint32_t sm32 = smem_u32(sm);

    int bid = blockIdx.x;
    int g, la;
    if      (bid <  48) { g = 1; la = bid;       }
    else if (bid <  96) { g = 2; la = bid -  48; }
    else if (bid < 112) { g = 0; la = bid -  96; }
    else                { g = 3; la = bid - 112; }
    int ly = la >> 1, col = la & 1;
    int K  = T_LDH[g];

    const char* A = reinterpret_cast<const char*>(
        g_Uh + T_UOFFX[g] + (size_t)ly * 128 * K);
    const char* B = reinterpret_cast<const char*>(
        g_wgh + T_WOFFX[g] + (size_t)col * 128 * K);

    float acc[4][8][4];
    mma_mainloop<128>(A, B, K, K * 2, sm32, acc);

    int lane = threadIdx.x & 31, wid = threadIdx.x >> 5;
    int wm = wid & 1, wn = wid >> 1;
    int g4 = lane >> 2, l2 = (lane & 3) * 2;
    int rbase = ly * 128 + wm * 64;
    int cbase = col * 128 + wn * 64;
    #pragma unroll
    for (int mt = 0; mt < 4; ++mt)
        #pragma unroll
        for (int nt = 0; nt < 8; ++nt) {
            int r0 = rbase + mt * 16 + g4;
            int cc = cbase + nt * 8 + l2;
            #pragma unroll
            for (int hh = 0; hh < 2; ++hh) {
                int r  = r0 + hh * 8;
                int jc = T_JBASE[g] + (r >> 10);
                int bb = r & 1023;
                *reinterpret_cast<float2*>(
                    g_prod + (size_t)jc * QP + (size_t)bb * 256 + cc) =
                    make_float2(acc[mt][nt][hh * 2], acc[mt][nt][hh * 2 + 1]);
            }
        }
}

// ---------------- final combine ----------------------------------------------
__global__ void k_combine(const float* __restrict__ b_left, float* __restrict__ out)
{
    int t = blockIdx.x * 256 + threadIdx.x;   // t = b*256 + mo
    int m = t & 255;
    float o[8];
    #pragma unroll
    for (int j = 0; j < 8; ++j) {
        float v = g_prod[j * QP + t];
        if (j == 0) v += b_left[m];
        o[j] = v * RSQRT2;
    }
    float4* op = reinterpret_cast<float4*>(out + (size_t)t * 8);
    op[0] = make_float4(o[0], o[1], o[2], o[3]);
    op[1] = make_float4(o[4], o[5], o[6], o[7]);
}

// ---------------- launch -----------------------------------------------------
#define DSMEM_BYTES (3 * 32768 + 1024)

extern "C" void kernel_launch(void* const* d_in, const int* in_sizes, int n_in,
                              void* d_out, int out_size)
{
    const float* x   = (const float*)d_in[0];
    const float* wr  = (const float*)d_in[1];
    const float* wl  = (const float*)d_in[2];
    const float* bl  = (const float*)d_in[3];
    const float* na  = (const float*)d_in[4];
    const float* gpw = (const float*)d_in[5];
    float* out = (float*)d_out;

    cudaFuncSetAttribute(k_lin_r, cudaFuncAttributeMaxDynamicSharedMemorySize, DSMEM_BYTES);
    cudaFuncSetAttribute(k_fused, cudaFuncAttributeMaxDynamicSharedMemorySize, DSMEM_BYTES);

    k_prep<<<1280, 256>>>(x, wr, wl);

    // 128 GEMM-tile CTAs + 256 gpw-prep CTAs in one launch
    k_lin_r<<<384, 256, DSMEM_BYTES>>>(gpw);

    k_build_U<<<1024, 256>>>(x, na);

    k_fused<<<128, 128, DSMEM_BYTES>>>();

    k_combine<<<1024, 256>>>(bl, out);
}